// round 6
// baseline (speedup 1.0000x reference)
#include <cuda_runtime.h>
#include <cuda_bf16.h>
#include <math.h>
#include <stdint.h>

#define BATCH   64
#define CH      96
#define HW      12544
#define MTOK    6
#define HEADS   4
#define RQ      24
#define DMODEL  192
#define QDIM    384
// SCALE * log2(e): scores feed ex2 directly
#define SCALE_F (0.10206207261596575f * 1.4426950408889634f)
#define SPLITS  14
#define CHUNK   896
#define TILE    128
#define TILES_PER 7
#define XSTR    136         // bf16 elems per X row (128 + 8 pad)
#define FSTR    132         // fp32 elems per staging row (128 + 4 pad)
#define QSTR    104         // bf16 elems per Q row (96 + 8 pad)
#define OSTR    100
#define WSTR    3200        // 32 * OSTR floats per warp partial

#define OFF_XF   0
#define OFF_Q    50688
#define OFF_X    57344       // 50688 + 6656
#define SMEM_TOT 84480       // 57344 + 96*136*2 (26112) + 1024 pad
#define OFF_L    51200       // epilogue overlay: after 4*WSTR*4 bytes

__device__ float g_Qp[4 * BATCH * RQ * CH];
__device__ float g_Lx[BATCH * SPLITS * RQ];
__device__ float g_Ox[BATCH * SPLITS * RQ * CH];

// ---------------------------------------------------------------------------
__device__ __forceinline__ uint32_t smem_u32(const void* p) {
    return (uint32_t)__cvta_generic_to_shared(p);
}
__device__ __forceinline__ void ldm_x4(uint32_t& r0, uint32_t& r1, uint32_t& r2,
                                       uint32_t& r3, uint32_t addr) {
    asm volatile("ldmatrix.sync.aligned.m8n8.x4.shared.b16 {%0,%1,%2,%3}, [%4];"
                 : "=r"(r0), "=r"(r1), "=r"(r2), "=r"(r3) : "r"(addr));
}
__device__ __forceinline__ void ldm_x4_t(uint32_t& r0, uint32_t& r1, uint32_t& r2,
                                         uint32_t& r3, uint32_t addr) {
    asm volatile("ldmatrix.sync.aligned.m8n8.x4.trans.shared.b16 {%0,%1,%2,%3}, [%4];"
                 : "=r"(r0), "=r"(r1), "=r"(r2), "=r"(r3) : "r"(addr));
}
__device__ __forceinline__ void mma16816(float* c, const uint32_t* a,
                                         uint32_t b0, uint32_t b1) {
    asm volatile("mma.sync.aligned.m16n8k16.row.col.f32.bf16.bf16.f32 "
                 "{%0,%1,%2,%3}, {%4,%5,%6,%7}, {%8,%9}, {%0,%1,%2,%3};"
                 : "+f"(c[0]), "+f"(c[1]), "+f"(c[2]), "+f"(c[3])
                 : "r"(a[0]), "r"(a[1]), "r"(a[2]), "r"(a[3]), "r"(b0), "r"(b1));
}
__device__ __forceinline__ void cpasync16(uint32_t dst, const void* src) {
    asm volatile("cp.async.cg.shared.global [%0], [%1], 16;" :: "r"(dst), "l"(src));
}
#define CP_COMMIT() asm volatile("cp.async.commit_group;" ::: "memory")
#define CP_WAIT0()  asm volatile("cp.async.wait_group 0;" ::: "memory")

__device__ __forceinline__ uint32_t pack_bf16(float a, float b) {
    __nv_bfloat162 h2 = __floats2bfloat162_rn(a, b);
    return *(uint32_t*)&h2;
}
__device__ __forceinline__ float ex2(float x) {
    float r;
    asm("ex2.approx.f32 %0, %1;" : "=f"(r) : "f"(x));
    return r;
}

// ---------------------------------------------------------------------------
// Kernel 1: Q projection, split-k x4. grid (BATCH, 4), 384 threads.
// Output pre-scaled by SCALE * log2(e) so attention can use ex2 directly.
// ---------------------------------------------------------------------------
__global__ __launch_bounds__(QDIM) void qproj_kernel(
    const float* __restrict__ z, const float* __restrict__ Wq,
    const float* __restrict__ bq)
{
    __shared__ float sz[MTOK * 48];
    const int b = blockIdx.x, kq = blockIdx.y, col = threadIdx.x;
    for (int i = col; i < MTOK * 48; i += QDIM) {
        const int m = i / 48, k = i - m * 48;
        sz[i] = z[b * MTOK * DMODEL + m * DMODEL + kq * 48 + k];
    }
    __syncthreads();

    float acc[MTOK];
    const float b0 = (kq == 0) ? bq[col] : 0.f;
    #pragma unroll
    for (int m = 0; m < MTOK; ++m) acc[m] = b0;

    const float* Wqp = Wq + (size_t)(kq * 48) * QDIM + col;
    #pragma unroll
    for (int k = 0; k < 48; ++k) {
        const float w = __ldg(Wqp + k * QDIM);
        #pragma unroll
        for (int m = 0; m < MTOK; ++m)
            acc[m] = fmaf(sz[m * 48 + k], w, acc[m]);
    }
    const int h = col / CH, c = col - h * CH;
    #pragma unroll
    for (int m = 0; m < MTOK; ++m)
        g_Qp[kq * (BATCH * RQ * CH) + (b * RQ + h * MTOK + m) * CH + c] = acc[m] * SCALE_F;
}

// ---------------------------------------------------------------------------
// Kernel 2: fixed-max (M=0) flash attention, P in registers, barrier-light.
// grid (SPLITS, BATCH), 128 threads = 4 warps, 2 CTAs/SM.
// Warp w owns spatial cols [32w, 32w+32); accumulates partial O[32x96] and
// partial row-sums L; single cross-warp reduction in the epilogue.
// ---------------------------------------------------------------------------
__global__ __launch_bounds__(128, 2) void attn_partial_kernel(const float* __restrict__ x)
{
    extern __shared__ char smem[];
    float*         sXf = (float*)(smem + OFF_XF);
    __nv_bfloat16* sQ  = (__nv_bfloat16*)(smem + OFF_Q);
    __nv_bfloat16* sX  = (__nv_bfloat16*)(smem + OFF_X);
    float*         sOr = (float*)smem;               // epilogue overlay
    float*         sLr = (float*)(smem + OFF_L);

    const int b = blockIdx.y, s = blockIdx.x;
    const int tid = threadIdx.x, lane = tid & 31, warp = tid >> 5;
    const int g = lane >> 2, tig = lane & 3;
    const int grp = lane >> 3;

    const uint32_t uQ  = smem_u32(sQ);
    const uint32_t uX  = smem_u32(sX);
    const uint32_t uXf = smem_u32(sXf);

    const float* xb = x + (size_t)b * CH * HW + (size_t)s * CHUNK;

    // ---- cp.async tile 0 ----
    #pragma unroll
    for (int r = 0; r < 24; ++r) {
        const int i = tid + 128 * r;
        const int c = i >> 5, n4 = (i & 31) << 2;
        cpasync16(uXf + (c * FSTR + n4) * 4, xb + (size_t)c * HW + n4);
    }
    CP_COMMIT();

    // ---- stage Q (sum 4 split-k partials -> bf16), rows 24..31 zero ----
    for (int i = tid; i < 32 * CH; i += 128) {
        const int r = i / CH, c = i - r * CH;
        float v = 0.f;
        if (r < RQ) {
            const int idx = (b * RQ + r) * CH + c;
            v = g_Qp[idx] + g_Qp[BATCH*RQ*CH + idx]
              + g_Qp[2*BATCH*RQ*CH + idx] + g_Qp[3*BATCH*RQ*CH + idx];
        }
        sQ[r * QSTR + c] = __float2bfloat16(v);
    }
    __syncthreads();

    // ---- hoist Q A-fragments (loop-invariant) ----
    uint32_t qf[2][6][4];
    #pragma unroll
    for (int i = 0; i < 6; ++i) {
        ldm_x4(qf[0][i][0], qf[0][i][1], qf[0][i][2], qf[0][i][3],
               uQ + (((lane & 15)     ) * QSTR + i * 16 + (lane >> 4) * 8) * 2);
        ldm_x4(qf[1][i][0], qf[1][i][1], qf[1][i][2], qf[1][i][3],
               uQ + ((16 + (lane & 15)) * QSTR + i * 16 + (lane >> 4) * 8) * 2);
    }

    float runL[4] = {0.f, 0.f, 0.f, 0.f};
    float oacc[2][12][4];
    #pragma unroll
    for (int mt = 0; mt < 2; ++mt)
        #pragma unroll
        for (int j = 0; j < 12; ++j)
            #pragma unroll
            for (int e = 0; e < 4; ++e) oacc[mt][j][e] = 0.f;

    for (int t = 0; t < TILES_PER; ++t) {
        CP_WAIT0();
        __syncthreads();   // staging landed; everyone done with sX of tile t-1

        // ---- convert staging fp32 -> bf16 sX ----
        #pragma unroll
        for (int r = 0; r < 24; ++r) {
            const int i = tid + 128 * r;
            const int c = i >> 5, n4 = (i & 31) << 2;
            float4 v = *reinterpret_cast<const float4*>(&sXf[c * FSTR + n4]);
            uint2 pk2;
            pk2.x = pack_bf16(v.x, v.y);
            pk2.y = pack_bf16(v.z, v.w);
            *reinterpret_cast<uint2*>(&sX[c * XSTR + n4]) = pk2;
        }
        __syncthreads();   // sX ready; sXf free

        // ---- prefetch tile t+1 ----
        if (t + 1 < TILES_PER) {
            const float* xt = xb + (t + 1) * TILE;
            #pragma unroll
            for (int r = 0; r < 24; ++r) {
                const int i = tid + 128 * r;
                const int c = i >> 5, n4 = (i & 31) << 2;
                cpasync16(uXf + (c * FSTR + n4) * 4, xt + (size_t)c * HW + n4);
            }
        }
        CP_COMMIT();

        // ---- QK: warp's 32 spatial cols, sc[mt][nt 0..3][4] ----
        float sc[2][4][4];
        #pragma unroll
        for (int mt = 0; mt < 2; ++mt)
            #pragma unroll
            for (int nt = 0; nt < 4; ++nt)
                #pragma unroll
                for (int e = 0; e < 4; ++e) sc[mt][nt][e] = 0.f;

        #pragma unroll
        for (int i = 0; i < 6; ++i) {
            #pragma unroll
            for (int q = 0; q < 2; ++q) {
                uint32_t bfr[4];
                const int row = i * 16 + (grp & 1) * 8 + (lane & 7);
                const int col = 32 * warp + 16 * q + (grp >> 1) * 8;
                ldm_x4_t(bfr[0], bfr[1], bfr[2], bfr[3], uX + (row * XSTR + col) * 2);
                mma16816(sc[0][2*q],     qf[0][i], bfr[0], bfr[1]);
                mma16816(sc[0][2*q + 1], qf[0][i], bfr[2], bfr[3]);
                mma16816(sc[1][2*q],     qf[1][i], bfr[0], bfr[1]);
                mma16816(sc[1][2*q + 1], qf[1][i], bfr[2], bfr[3]);
            }
        }

        // ---- P = 2^score (fixed max = 0), accumulate private row sums ----
        #pragma unroll
        for (int mt = 0; mt < 2; ++mt)
            #pragma unroll
            for (int nt = 0; nt < 4; ++nt)
                #pragma unroll
                for (int hl = 0; hl < 2; ++hl) {
                    float p0 = ex2(sc[mt][nt][hl*2]);
                    float p1 = ex2(sc[mt][nt][hl*2+1]);
                    sc[mt][nt][hl*2]   = p0;
                    sc[mt][nt][hl*2+1] = p1;
                    runL[mt*2 + hl] += p0 + p1;
                }

        // ---- PV: A-frags straight from score registers (2 k16 chunks) ----
        uint32_t pk[2][2][4];
        #pragma unroll
        for (int mt = 0; mt < 2; ++mt)
            #pragma unroll
            for (int kc = 0; kc < 2; ++kc) {
                pk[mt][kc][0] = pack_bf16(sc[mt][2*kc][0],   sc[mt][2*kc][1]);
                pk[mt][kc][1] = pack_bf16(sc[mt][2*kc][2],   sc[mt][2*kc][3]);
                pk[mt][kc][2] = pack_bf16(sc[mt][2*kc+1][0], sc[mt][2*kc+1][1]);
                pk[mt][kc][3] = pack_bf16(sc[mt][2*kc+1][2], sc[mt][2*kc+1][3]);
            }

        #pragma unroll
        for (int u = 0; u < 6; ++u) {
            #pragma unroll
            for (int kc = 0; kc < 2; ++kc) {
                uint32_t m0, m1, m2, m3;
                const int row = 16 * u + (grp >> 1) * 8 + (lane & 7);     // channel
                const int col = 32 * warp + 16 * kc + (grp & 1) * 8;      // spatial
                ldm_x4(m0, m1, m2, m3, uX + (row * XSTR + col) * 2);
                mma16816(oacc[0][2*u],     pk[0][kc], m0, m1);
                mma16816(oacc[0][2*u + 1], pk[0][kc], m2, m3);
                mma16816(oacc[1][2*u],     pk[1][kc], m0, m1);
                mma16816(oacc[1][2*u + 1], pk[1][kc], m2, m3);
            }
        }
    }

    // ---- epilogue: one cross-warp reduction for O and L ----
    __syncthreads();
    {
        float* my = sOr + warp * WSTR;
        #pragma unroll
        for (int mt = 0; mt < 2; ++mt)
            #pragma unroll
            for (int j = 0; j < 12; ++j) {
                const int r0 = 16*mt + g, c0 = 8*j + 2*tig;
                my[r0 * OSTR + c0]         = oacc[mt][j][0];
                my[r0 * OSTR + c0 + 1]     = oacc[mt][j][1];
                my[(r0+8) * OSTR + c0]     = oacc[mt][j][2];
                my[(r0+8) * OSTR + c0 + 1] = oacc[mt][j][3];
            }
        // L: reduce over tig lanes, then store per-warp row sums
        #pragma unroll
        for (int j = 0; j < 4; ++j) {
            runL[j] += __shfl_xor_sync(0xffffffffu, runL[j], 1);
            runL[j] += __shfl_xor_sync(0xffffffffu, runL[j], 2);
        }
        if (tig == 0) {
            sLr[warp * 32 + g]      = runL[0];
            sLr[warp * 32 + g + 8]  = runL[1];
            sLr[warp * 32 + g + 16] = runL[2];
            sLr[warp * 32 + g + 24] = runL[3];
        }
    }
    __syncthreads();

    const int base = (b * SPLITS + s) * RQ;
    for (int i = tid; i < RQ * CH; i += 128) {
        const int r = i / CH, c = i - r * CH;
        float sum = 0.f;
        #pragma unroll
        for (int w = 0; w < 4; ++w) sum += sOr[w * WSTR + r * OSTR + c];
        g_Ox[(base + r) * CH + c] = sum;
    }
    if (tid < RQ) {
        float L = 0.f;
        #pragma unroll
        for (int w = 0; w < 4; ++w) L += sLr[w * 32 + tid];
        g_Lx[base + tid] = L;
    }
}

// ---------------------------------------------------------------------------
// Kernel 3: combine split partials + output projection + residual.
// No per-split max: O = sum(O_s) / sum(L_s).
// ---------------------------------------------------------------------------
__global__ __launch_bounds__(DMODEL) void combine_proj_kernel(
    const float* __restrict__ z, const float* __restrict__ Wo,
    const float* __restrict__ bo, float* __restrict__ out)
{
    __shared__ float sOf[RQ * CH];
    __shared__ float sLi[RQ];
    const int b = blockIdx.x, tid = threadIdx.x;

    if (tid < RQ) {
        float L = 0.f;
        #pragma unroll
        for (int s = 0; s < SPLITS; ++s)
            L += g_Lx[(b * SPLITS + s) * RQ + tid];
        sLi[tid] = 1.f / L;
    }
    __syncthreads();

    for (int o = tid; o < RQ * CH; o += DMODEL) {
        const int q = o / CH, c = o - q * CH;
        float a = 0.f;
        #pragma unroll
        for (int s = 0; s < SPLITS; ++s)
            a += g_Ox[((b * SPLITS + s) * RQ + q) * CH + c];
        sOf[o] = a * sLi[q];
    }
    __syncthreads();

    float accv[MTOK];
    #pragma unroll
    for (int m = 0; m < MTOK; ++m)
        accv[m] = z[(b * MTOK + m) * DMODEL + tid] + bo[tid];

    for (int h = 0; h < HEADS; ++h) {
        #pragma unroll 4
        for (int c = 0; c < CH; ++c) {
            const float w = Wo[(h * CH + c) * DMODEL + tid];
            #pragma unroll
            for (int m = 0; m < MTOK; ++m)
                accv[m] = fmaf(sOf[(h * MTOK + m) * CH + c], w, accv[m]);
        }
    }
    #pragma unroll
    for (int m = 0; m < MTOK; ++m)
        out[(b * MTOK + m) * DMODEL + tid] = accv[m];
}

// ---------------------------------------------------------------------------
extern "C" void kernel_launch(void* const* d_in, const int* in_sizes, int n_in,
                              void* d_out, int out_size)
{
    const float* x  = (const float*)d_in[0];
    const float* z  = (const float*)d_in[1];
    const float* Wq = (const float*)d_in[2];
    const float* bq = (const float*)d_in[3];
    const float* Wo = (const float*)d_in[4];
    const float* bo = (const float*)d_in[5];
    float* out = (float*)d_out;

    cudaFuncSetAttribute(attn_partial_kernel,
                         cudaFuncAttributeMaxDynamicSharedMemorySize, SMEM_TOT);

    qproj_kernel<<<dim3(BATCH, 4), QDIM>>>(z, Wq, bq);
    attn_partial_kernel<<<dim3(SPLITS, BATCH), 128, SMEM_TOT>>>(x);
    combine_proj_kernel<<<BATCH, DMODEL>>>(z, Wo, bo, out);
}

// round 7
// speedup vs baseline: 1.4065x; 1.4065x over previous
#include <cuda_runtime.h>
#include <cuda_bf16.h>
#include <math.h>
#include <stdint.h>

#define BATCH   64
#define CH      96
#define HW      12544
#define MTOK    6
#define HEADS   4
#define RQ      24
#define DMODEL  192
#define QDIM    384
// SCALE * log2(e): scores feed ex2 directly
#define SCALE_F (0.10206207261596575f * 1.4426950408889634f)
#define SPLITS  14
#define CHUNK   896
#define TILE    128
#define TILES_PER 7
#define KQ      8           // qproj split-k
#define XSTR    136         // bf16 per X row (128+8): ldmatrix conflict-free
#define FSTR    132         // fp32 per staging row (128+4)
#define QSTR    104         // bf16 per Q row (96+8)
#define PSTR    136

#define OFF_XF   0
#define OFF_Q    50688
#define OFF_X    57344
#define OFF_P    83456
#define OFF_LR   92160
#define SMEM_TOT 93184

__device__ float g_Qp[KQ * BATCH * RQ * CH];
__device__ float g_Lx[BATCH * SPLITS * RQ];
__device__ float g_Ox[BATCH * SPLITS * RQ * CH];

// ---------------------------------------------------------------------------
__device__ __forceinline__ uint32_t smem_u32(const void* p) {
    return (uint32_t)__cvta_generic_to_shared(p);
}
__device__ __forceinline__ void ldm_x4(uint32_t& r0, uint32_t& r1, uint32_t& r2,
                                       uint32_t& r3, uint32_t addr) {
    asm volatile("ldmatrix.sync.aligned.m8n8.x4.shared.b16 {%0,%1,%2,%3}, [%4];"
                 : "=r"(r0), "=r"(r1), "=r"(r2), "=r"(r3) : "r"(addr));
}
__device__ __forceinline__ void ldm_x4_t(uint32_t& r0, uint32_t& r1, uint32_t& r2,
                                         uint32_t& r3, uint32_t addr) {
    asm volatile("ldmatrix.sync.aligned.m8n8.x4.trans.shared.b16 {%0,%1,%2,%3}, [%4];"
                 : "=r"(r0), "=r"(r1), "=r"(r2), "=r"(r3) : "r"(addr));
}
__device__ __forceinline__ void ldm_x2(uint32_t& r0, uint32_t& r1, uint32_t addr) {
    asm volatile("ldmatrix.sync.aligned.m8n8.x2.shared.b16 {%0,%1}, [%2];"
                 : "=r"(r0), "=r"(r1) : "r"(addr));
}
__device__ __forceinline__ void mma16816(float* c, const uint32_t* a,
                                         uint32_t b0, uint32_t b1) {
    asm volatile("mma.sync.aligned.m16n8k16.row.col.f32.bf16.bf16.f32 "
                 "{%0,%1,%2,%3}, {%4,%5,%6,%7}, {%8,%9}, {%0,%1,%2,%3};"
                 : "+f"(c[0]), "+f"(c[1]), "+f"(c[2]), "+f"(c[3])
                 : "r"(a[0]), "r"(a[1]), "r"(a[2]), "r"(a[3]), "r"(b0), "r"(b1));
}
__device__ __forceinline__ void cpasync16(uint32_t dst, const void* src) {
    asm volatile("cp.async.cg.shared.global [%0], [%1], 16;" :: "r"(dst), "l"(src));
}
#define CP_COMMIT() asm volatile("cp.async.commit_group;" ::: "memory")
#define CP_WAIT0()  asm volatile("cp.async.wait_group 0;" ::: "memory")

__device__ __forceinline__ uint32_t pack_bf16(float a, float b) {
    __nv_bfloat162 h2 = __floats2bfloat162_rn(a, b);
    return *(uint32_t*)&h2;
}
__device__ __forceinline__ float ex2(float x) {
    float r;
    asm("ex2.approx.f32 %0, %1;" : "=f"(r) : "f"(x));
    return r;
}

// ---------------------------------------------------------------------------
// Kernel 1: Q projection, split-k x8. grid (BATCH, KQ), 384 threads.
// Output pre-scaled by SCALE*log2(e) so attention uses ex2 directly.
// ---------------------------------------------------------------------------
__global__ __launch_bounds__(QDIM) void qproj_kernel(
    const float* __restrict__ z, const float* __restrict__ Wq,
    const float* __restrict__ bq)
{
    __shared__ float sz[MTOK * 24];
    const int b = blockIdx.x, kq = blockIdx.y, col = threadIdx.x;
    if (col < MTOK * 24) {
        const int m = col / 24, k = col - m * 24;
        sz[col] = z[b * MTOK * DMODEL + m * DMODEL + kq * 24 + k];
    }
    __syncthreads();

    float acc[MTOK];
    const float b0 = (kq == 0) ? bq[col] : 0.f;
    #pragma unroll
    for (int m = 0; m < MTOK; ++m) acc[m] = b0;

    const float* Wqp = Wq + (size_t)(kq * 24) * QDIM + col;
    #pragma unroll
    for (int k = 0; k < 24; ++k) {
        const float w = __ldg(Wqp + k * QDIM);
        #pragma unroll
        for (int m = 0; m < MTOK; ++m)
            acc[m] = fmaf(sz[m * 24 + k], w, acc[m]);
    }
    const int h = col / CH, c = col - h * CH;
    #pragma unroll
    for (int m = 0; m < MTOK; ++m)
        g_Qp[kq * (BATCH * RQ * CH) + (b * RQ + h * MTOK + m) * CH + c] = acc[m] * SCALE_F;
}

// ---------------------------------------------------------------------------
// Kernel 2: fixed-max flash attention, 8 warps, occ 2, 2 barriers/tile.
// Warp w: QK+exp for its 16 spatial cols (converts them itself);
// PV: m-tile warp&1, channels 24*(warp>>1) (R4 structure).
// ---------------------------------------------------------------------------
__global__ __launch_bounds__(256, 2) void attn_partial_kernel(const float* __restrict__ x)
{
    extern __shared__ char smem[];
    float*         sXf = (float*)(smem + OFF_XF);
    __nv_bfloat16* sQ  = (__nv_bfloat16*)(smem + OFF_Q);
    __nv_bfloat16* sX  = (__nv_bfloat16*)(smem + OFF_X);
    __nv_bfloat16* sP  = (__nv_bfloat16*)(smem + OFF_P);
    float*         sLr = (float*)(smem + OFF_LR);

    const int b = blockIdx.y, s = blockIdx.x;
    const int tid = threadIdx.x, lane = tid & 31, warp = tid >> 5;
    const int g = lane >> 2, tig = lane & 3;
    const int grp = lane >> 3;

    const uint32_t uQ  = smem_u32(sQ);
    const uint32_t uX  = smem_u32(sX);
    const uint32_t uP  = smem_u32(sP);
    const uint32_t uXf = smem_u32(sXf);

    const float* xb = x + (size_t)b * CH * HW + (size_t)s * CHUNK;

    // ---- cp.async tile 0 ----
    #pragma unroll
    for (int r = 0; r < 12; ++r) {
        const int i = tid + 256 * r;
        const int c = i >> 5, n4 = (i & 31) << 2;
        cpasync16(uXf + (c * FSTR + n4) * 4, xb + (size_t)c * HW + n4);
    }
    CP_COMMIT();

    // ---- stage Q (sum KQ split-k partials -> bf16), rows 24..31 zero ----
    for (int i = tid; i < 32 * CH; i += 256) {
        const int r = i / CH, c = i - r * CH;
        float v = 0.f;
        if (r < RQ) {
            const int idx = (b * RQ + r) * CH + c;
            #pragma unroll
            for (int k = 0; k < KQ; ++k) v += g_Qp[k * (BATCH * RQ * CH) + idx];
        }
        sQ[r * QSTR + c] = __float2bfloat16(v);
    }
    __syncthreads();

    // ---- hoist Q A-fragments ----
    uint32_t qf[2][6][4];
    #pragma unroll
    for (int i = 0; i < 6; ++i) {
        ldm_x4(qf[0][i][0], qf[0][i][1], qf[0][i][2], qf[0][i][3],
               uQ + (((lane & 15)     ) * QSTR + i * 16 + (lane >> 4) * 8) * 2);
        ldm_x4(qf[1][i][0], qf[1][i][1], qf[1][i][2], qf[1][i][3],
               uQ + ((16 + (lane & 15)) * QSTR + i * 16 + (lane >> 4) * 8) * 2);
    }

    float runL[4] = {0.f, 0.f, 0.f, 0.f};
    float oacc[12];
    #pragma unroll
    for (int j = 0; j < 12; ++j) oacc[j] = 0.f;

    const int mt_o  = warp & 1;
    const int cbase = 24 * (warp >> 1);
    const int cw    = 16 * warp;                 // own spatial-col base
    const int row16 = (lane & 7) + 8 * (lane >> 4);
    const int q4    = (lane >> 3) & 1;

    for (int t = 0; t < TILES_PER; ++t) {
        CP_WAIT0();
        __syncthreads();   // staging t landed; PV(t-1) done with sX/sP

        // ---- convert OWN 16 cols fp32 -> bf16 (conflict-free lane map) ----
        #pragma unroll
        for (int rr = 0; rr < 12; ++rr) {
            const int row = 16 * (rr >> 1) + row16;
            const int co  = cw + 8 * (rr & 1) + 4 * q4;
            float4 v = *reinterpret_cast<const float4*>(&sXf[row * FSTR + co]);
            uint2 pk2;
            pk2.x = pack_bf16(v.x, v.y);
            pk2.y = pack_bf16(v.z, v.w);
            *reinterpret_cast<uint2*>(&sX[row * XSTR + co]) = pk2;
        }
        __syncwarp();      // own-warp STS -> ldmatrix ordering

        // ---- QK on own cols ----
        float sc[2][2][4];
        #pragma unroll
        for (int mt = 0; mt < 2; ++mt)
            #pragma unroll
            for (int nt = 0; nt < 2; ++nt)
                #pragma unroll
                for (int e = 0; e < 4; ++e) sc[mt][nt][e] = 0.f;

        #pragma unroll
        for (int i = 0; i < 6; ++i) {
            uint32_t bfr[4];
            const int row = i * 16 + (grp & 1) * 8 + (lane & 7);
            const int col = cw + (grp >> 1) * 8;
            ldm_x4_t(bfr[0], bfr[1], bfr[2], bfr[3], uX + (row * XSTR + col) * 2);
            mma16816(sc[0][0], qf[0][i], bfr[0], bfr[1]);
            mma16816(sc[0][1], qf[0][i], bfr[2], bfr[3]);
            mma16816(sc[1][0], qf[1][i], bfr[0], bfr[1]);
            mma16816(sc[1][1], qf[1][i], bfr[2], bfr[3]);
        }

        // ---- P = 2^score (fixed max), private L, P -> smem ----
        #pragma unroll
        for (int mt = 0; mt < 2; ++mt)
            #pragma unroll
            for (int nt = 0; nt < 2; ++nt)
                #pragma unroll
                for (int hl = 0; hl < 2; ++hl) {
                    float p0 = ex2(sc[mt][nt][hl*2]);
                    float p1 = ex2(sc[mt][nt][hl*2+1]);
                    runL[mt*2 + hl] += p0 + p1;
                    const int row = 16*mt + g + 8*hl;
                    const int col = cw + 8*nt + 2*tig;
                    *reinterpret_cast<__nv_bfloat162*>(&sP[row * PSTR + col]) =
                        __floats2bfloat162_rn(p0, p1);
                }
        __syncthreads();   // all cols of sX + sP ready; sXf consumed

        // ---- prefetch tile t+1 ----
        if (t + 1 < TILES_PER) {
            const float* xt = xb + (t + 1) * TILE;
            #pragma unroll
            for (int r = 0; r < 12; ++r) {
                const int i = tid + 256 * r;
                const int c = i >> 5, n4 = (i & 31) << 2;
                cpasync16(uXf + (c * FSTR + n4) * 4, xt + (size_t)c * HW + n4);
            }
        }
        CP_COMMIT();

        // ---- PV (overlaps DRAM prefetch) ----
        #pragma unroll
        for (int i = 0; i < 8; ++i) {
            uint32_t a[4], b01[4], b2[2];
            ldm_x4(a[0], a[1], a[2], a[3],
                   uP + ((16*mt_o + (lane & 15)) * PSTR + i * 16 + (lane >> 4) * 8) * 2);
            {
                const int row = cbase + (grp >> 1) * 8 + (lane & 7);
                const int col = i * 16 + (grp & 1) * 8;
                ldm_x4(b01[0], b01[1], b01[2], b01[3], uX + (row * XSTR + col) * 2);
            }
            {
                const int row = cbase + 16 + (lane & 7);
                const int col = i * 16 + ((lane >> 3) & 1) * 8;
                ldm_x2(b2[0], b2[1], uX + (row * XSTR + col) * 2);
            }
            mma16816(oacc + 0, a, b01[0], b01[1]);
            mma16816(oacc + 4, a, b01[2], b01[3]);
            mma16816(oacc + 8, a, b2[0],  b2[1]);
        }
    }

    // ---- epilogue ----
    const int base = (b * SPLITS + s) * RQ;
    {
        const int r0 = 16*mt_o + g;              // < 24 always
        #pragma unroll
        for (int j = 0; j < 3; ++j) {
            const int c0 = cbase + 8*j + 2*tig;
            g_Ox[(base + r0) * CH + c0]     = oacc[4*j+0];
            g_Ox[(base + r0) * CH + c0 + 1] = oacc[4*j+1];
        }
        if (mt_o == 0) {
            const int r1 = g + 8;
            #pragma unroll
            for (int j = 0; j < 3; ++j) {
                const int c0 = cbase + 8*j + 2*tig;
                g_Ox[(base + r1) * CH + c0]     = oacc[4*j+2];
                g_Ox[(base + r1) * CH + c0 + 1] = oacc[4*j+3];
            }
        }
    }
    // L: reduce tig lanes, per-warp rows to smem, then cross-warp sum
    #pragma unroll
    for (int j = 0; j < 4; ++j) {
        runL[j] += __shfl_xor_sync(0xffffffffu, runL[j], 1);
        runL[j] += __shfl_xor_sync(0xffffffffu, runL[j], 2);
    }
    if (tig == 0) {
        sLr[warp * 32 + g]      = runL[0];
        sLr[warp * 32 + g + 8]  = runL[1];
        sLr[warp * 32 + g + 16] = runL[2];
        sLr[warp * 32 + g + 24] = runL[3];
    }
    __syncthreads();
    if (tid < RQ) {
        float L = 0.f;
        #pragma unroll
        for (int w = 0; w < 8; ++w) L += sLr[w * 32 + tid];
        g_Lx[base + tid] = L;
    }
}

// ---------------------------------------------------------------------------
// Kernel 3: combine split partials + output projection + residual.
// ---------------------------------------------------------------------------
__global__ __launch_bounds__(DMODEL) void combine_proj_kernel(
    const float* __restrict__ z, const float* __restrict__ Wo,
    const float* __restrict__ bo, float* __restrict__ out)
{
    __shared__ float sOf[RQ * CH];
    __shared__ float sLi[RQ];
    const int b = blockIdx.x, tid = threadIdx.x;

    if (tid < RQ) {
        float L = 0.f;
        #pragma unroll
        for (int s = 0; s < SPLITS; ++s)
            L += g_Lx[(b * SPLITS + s) * RQ + tid];
        sLi[tid] = 1.f / L;
    }
    __syncthreads();

    for (int o = tid; o < RQ * CH; o += DMODEL) {
        const int q = o / CH, c = o - q * CH;
        float a = 0.f;
        #pragma unroll
        for (int s = 0; s < SPLITS; ++s)
            a += g_Ox[((b * SPLITS + s) * RQ + q) * CH + c];
        sOf[o] = a * sLi[q];
    }
    __syncthreads();

    float accv[MTOK];
    #pragma unroll
    for (int m = 0; m < MTOK; ++m)
        accv[m] = z[(b * MTOK + m) * DMODEL + tid] + bo[tid];

    for (int h = 0; h < HEADS; ++h) {
        #pragma unroll 4
        for (int c = 0; c < CH; ++c) {
            const float w = Wo[(h * CH + c) * DMODEL + tid];
            #pragma unroll
            for (int m = 0; m < MTOK; ++m)
                accv[m] = fmaf(sOf[(h * MTOK + m) * CH + c], w, accv[m]);
        }
    }
    #pragma unroll
    for (int m = 0; m < MTOK; ++m)
        out[(b * MTOK + m) * DMODEL + tid] = accv[m];
}

// ---------------------------------------------------------------------------
extern "C" void kernel_launch(void* const* d_in, const int* in_sizes, int n_in,
                              void* d_out, int out_size)
{
    const float* x  = (const float*)d_in[0];
    const float* z  = (const float*)d_in[1];
    const float* Wq = (const float*)d_in[2];
    const float* bq = (const float*)d_in[3];
    const float* Wo = (const float*)d_in[4];
    const float* bo = (const float*)d_in[5];
    float* out = (float*)d_out;

    cudaFuncSetAttribute(attn_partial_kernel,
                         cudaFuncAttributeMaxDynamicSharedMemorySize, SMEM_TOT);

    qproj_kernel<<<dim3(BATCH, KQ), QDIM>>>(z, Wq, bq);
    attn_partial_kernel<<<dim3(SPLITS, BATCH), 256, SMEM_TOT>>>(x);
    combine_proj_kernel<<<BATCH, DMODEL>>>(z, Wo, bo, out);
}